// round 14
// baseline (speedup 1.0000x reference)
#include <cuda_runtime.h>
#include <math.h>

#define NB 4
#define NA 262144
#define PRE 4000
#define POST 1000
#define NBIN 16384
#define BSHIFT 18
#define KCAP 8192
#define CPB 64                // CTAs per batch in k_main
#define K1THR 256
#define CHUNK4 (NA / CPB / 4) // 1024 float4 per CTA slice
#define PCAP 8192
#define XBINS 256
#define XORG (-8.0f)
#define XSCL 4.0f
#define SLOTS_PER_CTA 4
#define PB_CTA (PRE / SLOTS_PER_CTA)  // 1000 pairs-CTAs per batch

static __device__ const float NMS_TH = 0.3f;
static __device__ const float AUG = 0.2f;

// ---- global scratch (zero-init; kernel2 re-zeroes everything dirtied) ----
__device__ unsigned g_hist[NB][NBIN];
__device__ unsigned g_bincnt[NB][NBIN];
__device__ int g_base[NB][NBIN];
__device__ unsigned g_selbin[NB];
__device__ int g_cc[NB];
__device__ int g_done1[NB];
__device__ int g_done2[NB];
__device__ int g_done3[NB];
__device__ int g_doneP[NB];
__device__ int g_flag1[NB];
__device__ unsigned long long g_keys2[NB][KCAP];
__device__ float4 g_geoA[NB][PRE];   // lox, hix, loy, hiy   (by rank)
__device__ float4 g_geoB[NB][PRE];   // loz, hiz, vol, rank  (by rank)
__device__ float4 g_sA[NB][PRE];     // spatially sorted copy
__device__ float4 g_sB[NB][PRE];
__device__ unsigned g_xcnt[NB][XBINS];
__device__ unsigned g_xfill[NB][XBINS];
__device__ int g_xbase[NB][XBINS + 1];
__device__ float g_box[NB][PRE][7];
__device__ float g_score[NB][PRE];
__device__ unsigned g_pairs[NB][PCAP];
__device__ int g_pcnt[NB];

__device__ __forceinline__ unsigned mapf(float v) {
    unsigned u = __float_as_uint(v);
    return (u & 0x80000000u) ? ~u : (u | 0x80000000u);
}
__device__ __forceinline__ float unmapf(unsigned m) {
    return __uint_as_float((m & 0x80000000u) ? (m & 0x7FFFFFFFu) : ~m);
}
__device__ __forceinline__ int xcell(float v) {
    int c = (int)((v - XORG) * XSCL);
    return max(0, min(XBINS - 1, c));
}

__device__ __forceinline__ void decode_box(const float* __restrict__ rg,
                                           const float* __restrict__ an,
                                           float* bx) {
    float xa = an[0], ya = an[1], za = an[2];
    float wa = an[3], la = an[4], ha = an[5], ra = an[6];
    float diag = sqrtf(wa * wa + la * la);
    bx[0] = rg[0] * diag + xa;
    bx[1] = rg[1] * diag + ya;
    bx[2] = rg[2] * ha + za;
    bx[3] = expf(rg[3]) * wa;
    bx[4] = expf(rg[4]) * la;
    bx[5] = expf(rg[5]) * ha;
    bx[6] = rg[6] + ra;
}

// ===================== K1: hist -> scan -> scatter -> rank -> spatial scatter =====================
// 256 CTAs total (64/batch), 64KB smem -> 3 CTAs/SM -> all co-resident: spin barriers are safe.
__global__ void __launch_bounds__(K1THR) k_main(
    const float* __restrict__ obj,
    const float* __restrict__ reg,
    const float* __restrict__ anc)
{
    __shared__ unsigned sh[NBIN];         // 64 KB
    __shared__ unsigned ssum[K1THR];
    __shared__ int s_base[XBINS + 1];
    __shared__ int s_last;
    const int b = blockIdx.x / CPB;
    const int c = blockIdx.x % CPB;
    const int tid = threadIdx.x;

    // ---- phase 1: smem histogram + merge ----
    for (int i = tid; i < NBIN; i += K1THR) sh[i] = 0u;
    __syncthreads();
    const float4* o4 = (const float4*)(obj + (size_t)b * NA) + (size_t)c * CHUNK4;
    for (int i = tid; i < CHUNK4; i += K1THR) {
        float4 v = o4[i];
        atomicAdd(&sh[mapf(v.x) >> BSHIFT], 1u);
        atomicAdd(&sh[mapf(v.y) >> BSHIFT], 1u);
        atomicAdd(&sh[mapf(v.z) >> BSHIFT], 1u);
        atomicAdd(&sh[mapf(v.w) >> BSHIFT], 1u);
    }
    __syncthreads();
    for (int i = tid; i < NBIN; i += K1THR) {
        unsigned cnt = sh[i];
        if (cnt) atomicAdd(&g_hist[b][i], cnt);
    }
    __threadfence();
    __syncthreads();
    if (tid == 0) s_last = (atomicAdd(&g_done1[b], 1) == CPB - 1) ? 1 : 0;
    __syncthreads();
    if (s_last) {
        // suffix scan over 16384 bins (re-read hist, no reg cache)
        const int CW = NBIN / K1THR;   // 64
        const int bi = tid * CW;
        unsigned csum = 0;
        for (int k = 0; k < CW; ++k) csum += __ldcg(&g_hist[b][bi + k]);
        unsigned orig = csum;
        ssum[tid] = csum;
        __syncthreads();
        for (int d = 1; d < K1THR; d <<= 1) {
            unsigned v = (tid + d < K1THR) ? ssum[tid + d] : 0u;
            __syncthreads();
            ssum[tid] += v;
            __syncthreads();
        }
        unsigned run = ssum[tid] - orig;
        for (int k = CW - 1; k >= 0; --k) {
            int bin = bi + k;
            unsigned cnt = __ldcg(&g_hist[b][bin]);
            g_base[b][bin] = (int)run;
            unsigned nb2 = run + cnt;
            if (run < PRE && nb2 >= PRE) {
                g_selbin[b] = (unsigned)bin;
                g_cc[b] = (int)(nb2 < KCAP ? nb2 : KCAP);
            }
            run = nb2;
        }
        __threadfence();
        __syncthreads();
        if (tid == 0) atomicExch(&g_flag1[b], 1);
    } else {
        if (tid == 0) { while (atomicAdd(&g_flag1[b], 0) == 0) {} }
    }
    __syncthreads();
    __threadfence();

    // ---- phase 2: binned scatter of candidates ----
    {
        const unsigned T = ((unsigned)atomicAdd((int*)&g_selbin[b], 0)) << BSHIFT;
        for (int i = tid; i < CHUNK4; i += K1THR) {
            float4 v = o4[i];
            unsigned uu[4] = {mapf(v.x), mapf(v.y), mapf(v.z), mapf(v.w)};
            int e0 = (c * CHUNK4 + i) * 4;
            #pragma unroll
            for (int q = 0; q < 4; ++q) {
                if (uu[q] >= T) {
                    int bin = uu[q] >> BSHIFT;
                    int slot = g_base[b][bin] + (int)atomicAdd(&g_bincnt[b][bin], 1u);
                    if (slot < KCAP)
                        g_keys2[b][slot] =
                            ((unsigned long long)uu[q] << 32) | (unsigned)(~(e0 + q));
                }
            }
        }
    }
    __threadfence();
    __syncthreads();
    if (tid == 0) {
        atomicAdd(&g_done2[b], 1);
        while (atomicAdd(&g_done2[b], 0) < CPB) {}
    }
    __syncthreads();
    __threadfence();

    // ---- phase 3: two-level exact rank + decode + x-cell count ----
    {
        const int cc = g_cc[b];
        const int s = c * K1THR + tid;
        if (s < cc) {
            const unsigned long long me = __ldcg(&g_keys2[b][s]);
            const unsigned u = (unsigned)(me >> 32);
            const int bin = (int)(u >> BSHIFT);
            const int lo = g_base[b][bin];
            int hi = lo + (int)__ldcg(&g_hist[b][bin]);
            if (hi > cc) hi = cc;
            int rank = lo;
            for (int t = lo; t < hi; ++t) rank += (__ldcg(&g_keys2[b][t]) > me);

            if (rank < PRE) {
                int idx = (int)(~(unsigned)(me & 0xFFFFFFFFull));
                const float* rg = reg + ((size_t)b * NA + idx) * 7;
                const float* an = anc + ((size_t)b * NA + idx) * 7;
                float bx[7];
                decode_box(rg, an, bx);
                #pragma unroll
                for (int q = 0; q < 7; ++q) g_box[b][rank][q] = bx[q];
                g_score[b][rank] = 1.0f / (1.0f + expf(-unmapf(u)));
                float sx = fmaxf(bx[3], AUG);
                float sy = fmaxf(bx[4], AUG);
                float sz = fmaxf(bx[5], AUG);
                float lox = bx[0] - sx * 0.5f;
                g_geoA[b][rank] = make_float4(lox, bx[0] + sx * 0.5f,
                                              bx[1] - sy * 0.5f, bx[1] + sy * 0.5f);
                g_geoB[b][rank] = make_float4(bx[2], bx[2] + sz, sx * sy * sz,
                                              __int_as_float(rank));
                atomicAdd(&g_xcnt[b][xcell(lox)], 1u);
            }
        }
    }
    __threadfence();
    __syncthreads();
    if (tid == 0) {
        atomicAdd(&g_done3[b], 1);
        while (atomicAdd(&g_done3[b], 0) < CPB) {}
    }
    __syncthreads();
    __threadfence();

    // ---- phase 4: per-CTA cell prefix + parallel spatial scatter ----
    {
        unsigned cnt = (unsigned)atomicAdd((int*)&g_xcnt[b][tid], 0);  // tid == cell
        ssum[tid] = cnt;
        for (int d = 1; d < XBINS; d <<= 1) {
            __syncthreads();
            unsigned v = (tid >= d) ? ssum[tid - d] : 0u;
            __syncthreads();
            ssum[tid] += v;
        }
        __syncthreads();
        s_base[tid] = (int)(ssum[tid] - cnt);   // exclusive
        if (tid == XBINS - 1) s_base[XBINS] = (int)ssum[XBINS - 1];
        __syncthreads();
        if (c == 0) {
            g_xbase[b][tid] = s_base[tid];
            if (tid == XBINS - 1) g_xbase[b][XBINS] = s_base[XBINS];
        }
        const int g = c * K1THR + tid;
        if (g < PRE) {
            float4 A = __ldcg((const float4*)&g_geoA[b][g]);
            int cell = xcell(A.x);
            int pos = s_base[cell] + (int)atomicAdd(&g_xfill[b][cell], 1u);
            g_sA[b][pos] = A;
            g_sB[b][pos] = __ldcg((const float4*)&g_geoB[b][g]);
        }
    }
}

// ===================== K2: contiguous sweep pairs, last CTA resolves + outputs =====================
__global__ void __launch_bounds__(256) k_pairs_final(float* __restrict__ out) {
    __shared__ int s_last;
    const int tid = threadIdx.x;
    const int b = blockIdx.x / PB_CTA;
    const int cslice = blockIdx.x % PB_CTA;
    const int s = cslice * SLOTS_PER_CTA + (tid >> 6);   // spatial slot
    const int half = (tid >> 5) & 1;
    const int lane = tid & 31;

    {
        const float4 pA = g_sA[b][s];
        const float4 pB = g_sB[b][s];
        const int rp = __float_as_int(pB.w);
        const int end = g_xbase[b][xcell(pA.y) + 1];
        for (int q = s + 1 + half * 32 + lane; q < end; q += 64) {
            float4 qA = g_sA[b][q];
            float dxx = fminf(pA.y, qA.y) - fmaxf(pA.x, qA.x);
            if (dxx <= 0.f) continue;
            float dyy = fminf(pA.w, qA.w) - fmaxf(pA.z, qA.z);
            if (dyy <= 0.f) continue;
            float4 qB = g_sB[b][q];
            float dzz = fminf(pB.y, qB.y) - fmaxf(pB.x, qB.x);
            if (dzz <= 0.f) continue;
            float inter = dxx * dyy * dzz;
            float iou = inter / fmaxf(pB.z + qB.z - inter, 1e-8f);
            if (iou > NMS_TH) {
                int rq = __float_as_int(qB.w);
                int i = min(rp, rq), j = max(rp, rq);
                int p = atomicAdd(&g_pcnt[b], 1);
                if (p < PCAP) g_pairs[b][p] = ((unsigned)i << 16) | (unsigned)j;
            }
        }
    }

    // idle-time rezero of this batch's scratch for the next replay
    for (int i = cslice * 256 + tid; i < NBIN; i += PB_CTA * 256) {
        g_hist[b][i] = 0u;
        g_bincnt[b][i] = 0u;
    }
    if (cslice == 0) {
        g_xcnt[b][tid] = 0u;
        g_xfill[b][tid] = 0u;
        if (tid == 0) {
            g_flag1[b] = 0;
            g_done1[b] = 0;
            g_done2[b] = 0;
            g_done3[b] = 0;
        }
    }

    __threadfence();
    __syncthreads();
    if (tid == 0) s_last = (atomicAdd(&g_doneP[b], 1) == PB_CTA - 1) ? 1 : 0;
    __syncthreads();
    if (!s_last) return;

    // ---- resolve + output (one CTA per batch) ----
    __shared__ unsigned pr[PCAP];
    __shared__ unsigned keepw[128];
    __shared__ int scan[126];
    __shared__ int order[POST];
    __shared__ int s_nk;

    int m = __ldcg(&g_pcnt[b]);
    if (m > PCAP) m = PCAP;
    int n2 = 32;
    while (n2 < m) n2 <<= 1;
    for (int i = tid; i < n2; i += 256)
        pr[i] = (i < m) ? __ldcg(&g_pairs[b][i]) : 0xFFFFFFFFu;
    __syncthreads();

    for (int k = 2; k <= n2; k <<= 1) {
        for (int jj = k >> 1; jj > 0; jj >>= 1) {
            for (int t = tid; t < n2; t += 256) {
                int ixj = t ^ jj;
                if (ixj > t) {
                    unsigned a = pr[t], c2 = pr[ixj];
                    bool up = ((t & k) == 0);
                    if (up ? (a > c2) : (a < c2)) { pr[t] = c2; pr[ixj] = a; }
                }
            }
            __syncthreads();
        }
    }

    for (int t = tid; t < 128; t += 256) keepw[t] = 0xFFFFFFFFu;
    __syncthreads();

    if (tid == 0) {
        for (int p = 0; p < m; ++p) {
            unsigned u = pr[p];
            int i = (int)(u >> 16);
            int j = (int)(u & 0xFFFFu);
            if ((keepw[i >> 5] >> (i & 31)) & 1u)
                keepw[j >> 5] &= ~(1u << (j & 31));
        }
        int run = 0;
        for (int w = 0; w < 125; ++w) {
            scan[w] = run;
            run += __popc(keepw[w]);
        }
        s_nk = run < POST ? run : POST;
        g_pcnt[b] = 0;
        g_doneP[b] = 0;
    }
    __syncthreads();

    if (tid < 125) {
        unsigned w = keepw[tid];
        int base = scan[tid];
        while (w && base < POST) {
            int l = __ffs(w) - 1;
            w &= w - 1;
            order[base] = tid * 32 + l;
            ++base;
        }
    }
    __syncthreads();

    const int nk = s_nk;
    float* outb = out + (size_t)b * POST * 8;
    for (int r = tid; r < POST; r += 256) {
        float row[8];
        if (r < nk) {
            int rr = order[r];
            #pragma unroll
            for (int q = 0; q < 7; ++q) row[q] = g_box[b][rr][q];
            row[7] = g_score[b][rr];
        } else {
            #pragma unroll
            for (int q = 0; q < 8; ++q) row[q] = 0.f;
        }
        float4* o4 = (float4*)(outb + (size_t)r * 8);
        o4[0] = make_float4(row[0], row[1], row[2], row[3]);
        o4[1] = make_float4(row[4], row[5], row[6], row[7]);
    }
}

extern "C" void kernel_launch(void* const* d_in, const int* in_sizes, int n_in,
                              void* d_out, int out_size) {
    const float* obj = (const float*)d_in[0];
    const float* reg = (const float*)d_in[1];
    const float* anc = (const float*)d_in[2];
    float* out = (float*)d_out;

    k_main<<<NB * CPB, K1THR>>>(obj, reg, anc);
    k_pairs_final<<<NB * PB_CTA, 256>>>(out);
}

// round 15
// speedup vs baseline: 1.3853x; 1.3853x over previous
#include <cuda_runtime.h>
#include <math.h>

#define NB 4
#define NA 262144
#define PRE 4000
#define POST 1000
#define NBIN 16384
#define BSHIFT 18
#define KCAP 8192
#define HCTA 64
#define HTHR 256
#define SCTA 128
#define STHR 256
#define RTHR 1024
#define RCTA (KCAP / RTHR)   // 8 CTAs per batch
#define PCAP 8192
#define XBINS 256
#define XORG (-8.0f)
#define XSCL 4.0f
#define SLOTS_PER_CTA 4              // 4 slots * 2 subwarps * 32 lanes = 256 thr
#define PB_CTA (PRE / SLOTS_PER_CTA) // 1000 pairs-CTAs per batch

static __device__ const float NMS_TH = 0.3f;
static __device__ const float AUG = 0.2f;

// ---- global scratch (zero-init; final tail re-zeroes everything dirtied) ----
__device__ unsigned g_hist[NB][NBIN];
__device__ unsigned g_bincnt[NB][NBIN];
__device__ int g_base[NB][NBIN];
__device__ unsigned g_selbin[NB];
__device__ int g_cc[NB];
__device__ int g_done1[NB];
__device__ int g_done2[NB];
__device__ int g_done3[NB];
__device__ unsigned long long g_keys2[NB][KCAP];
__device__ float4 g_geoA[NB][PRE];   // lox, hix, loy, hiy   (by rank)
__device__ float4 g_geoB[NB][PRE];   // loz, hiz, vol, rank  (by rank)
__device__ float4 g_sA[NB][PRE];     // spatially sorted copy
__device__ float4 g_sB[NB][PRE];
__device__ unsigned g_xcnt[NB][XBINS];
__device__ int g_xbase[NB][XBINS + 1];
__device__ float g_box[NB][PRE][7];
__device__ float g_score[NB][PRE];
__device__ unsigned g_pairs[NB][PCAP];
__device__ int g_pcnt[NB];

__device__ __forceinline__ unsigned mapf(float v) {
    unsigned u = __float_as_uint(v);
    return (u & 0x80000000u) ? ~u : (u | 0x80000000u);
}
__device__ __forceinline__ float unmapf(unsigned m) {
    return __uint_as_float((m & 0x80000000u) ? (m & 0x7FFFFFFFu) : ~m);
}
__device__ __forceinline__ int xcell(float v) {
    int c = (int)((v - XORG) * XSCL);
    return max(0, min(XBINS - 1, c));
}

__device__ __forceinline__ void decode_box(const float* __restrict__ rg,
                                           const float* __restrict__ an,
                                           float* bx) {
    float xa = an[0], ya = an[1], za = an[2];
    float wa = an[3], la = an[4], ha = an[5], ra = an[6];
    float diag = sqrtf(wa * wa + la * la);
    bx[0] = rg[0] * diag + xa;
    bx[1] = rg[1] * diag + ya;
    bx[2] = rg[2] * ha + za;
    bx[3] = expf(rg[3]) * wa;
    bx[4] = expf(rg[4]) * la;
    bx[5] = expf(rg[5]) * ha;
    bx[6] = rg[6] + ra;
}

// ================= K1: smem histogram + last-CTA suffix scan =================
__global__ void __launch_bounds__(HTHR) k_hist(const float* __restrict__ obj) {
    __shared__ unsigned sh[NBIN];
    __shared__ int s_last;
    const int b = blockIdx.x / HCTA;
    const int c = blockIdx.x % HCTA;
    const int tid = threadIdx.x;
    for (int i = tid; i < NBIN; i += HTHR) sh[i] = 0u;
    __syncthreads();
    const int CHUNK = NA / HCTA / 4;
    const float4* o4 = (const float4*)(obj + (size_t)b * NA) + (size_t)c * CHUNK;
    for (int i = tid; i < CHUNK; i += HTHR) {
        float4 v = o4[i];
        atomicAdd(&sh[mapf(v.x) >> BSHIFT], 1u);
        atomicAdd(&sh[mapf(v.y) >> BSHIFT], 1u);
        atomicAdd(&sh[mapf(v.z) >> BSHIFT], 1u);
        atomicAdd(&sh[mapf(v.w) >> BSHIFT], 1u);
    }
    __syncthreads();
    for (int i = tid; i < NBIN; i += HTHR) {
        unsigned cnt = sh[i];
        if (cnt) atomicAdd(&g_hist[b][i], cnt);
    }
    __threadfence();
    if (tid == 0) s_last = (atomicAdd(&g_done1[b], 1) == HCTA - 1) ? 1 : 0;
    __syncthreads();
    if (!s_last) return;

    __shared__ unsigned ssum[HTHR];
    const int CW = NBIN / HTHR;   // 64
    const int bi = tid * CW;
    unsigned loc[CW];
    unsigned csum = 0;
    #pragma unroll
    for (int k = 0; k < CW; ++k) {
        loc[k] = __ldcg(&g_hist[b][bi + k]);
        csum += loc[k];
    }
    unsigned orig = csum;
    ssum[tid] = csum;
    __syncthreads();
    for (int d = 1; d < HTHR; d <<= 1) {
        unsigned v = (tid + d < HTHR) ? ssum[tid + d] : 0u;
        __syncthreads();
        ssum[tid] += v;
        __syncthreads();
    }
    unsigned run = ssum[tid] - orig;
    for (int k = CW - 1; k >= 0; --k) {
        int bin = bi + k;
        g_base[b][bin] = (int)run;
        unsigned nb2 = run + loc[k];
        if (run < PRE && nb2 >= PRE) {
            g_selbin[b] = (unsigned)bin;
            g_cc[b] = (int)(nb2 < KCAP ? nb2 : KCAP);
        }
        run = nb2;
    }
}

// ================= K2: binned scatter of candidates =================
__global__ void __launch_bounds__(STHR) k_scatter(const float* __restrict__ obj) {
    const int b = blockIdx.x / SCTA;
    const int c = blockIdx.x % SCTA;
    const unsigned T = g_selbin[b] << BSHIFT;
    const int CHUNK = NA / SCTA / 4;
    const float4* o4 = (const float4*)(obj + (size_t)b * NA) + (size_t)c * CHUNK;
    for (int i = threadIdx.x; i < CHUNK; i += STHR) {
        float4 v = o4[i];
        unsigned uu[4] = {mapf(v.x), mapf(v.y), mapf(v.z), mapf(v.w)};
        int e0 = (c * CHUNK + i) * 4;
        #pragma unroll
        for (int q = 0; q < 4; ++q) {
            if (uu[q] >= T) {
                int bin = uu[q] >> BSHIFT;
                int slot = g_base[b][bin] + (int)atomicAdd(&g_bincnt[b][bin], 1u);
                if (slot < KCAP)
                    g_keys2[b][slot] =
                        ((unsigned long long)uu[q] << 32) | (unsigned)(~(e0 + q));
            }
        }
    }
}

// ================= K3: rank + decode (1024 thr), last CTA does wide cells tail =================
__global__ void __launch_bounds__(RTHR) k_rank(
    const float* __restrict__ reg, const float* __restrict__ anc)
{
    __shared__ int s_last;
    const int b = blockIdx.x / RCTA;
    const int c = blockIdx.x % RCTA;
    const int tid = threadIdx.x;
    const int cc = g_cc[b];
    const int s = c * RTHR + tid;

    if (s < cc) {
        const unsigned long long me = g_keys2[b][s];
        const unsigned u = (unsigned)(me >> 32);
        const int bin = (int)(u >> BSHIFT);
        const int lo = g_base[b][bin];
        int hi = lo + (int)g_hist[b][bin];
        if (hi > cc) hi = cc;
        int rank = lo;
        const unsigned long long* kb = &g_keys2[b][0];
        int t = lo;
        for (; t + 4 <= hi; t += 4) {
            unsigned long long k0 = kb[t], k1 = kb[t + 1], k2 = kb[t + 2], k3 = kb[t + 3];
            rank += (k0 > me) + (k1 > me) + (k2 > me) + (k3 > me);
        }
        for (; t < hi; ++t) rank += (kb[t] > me);

        if (rank < PRE) {
            int idx = (int)(~(unsigned)(me & 0xFFFFFFFFull));
            const float* rg = reg + ((size_t)b * NA + idx) * 7;
            const float* an = anc + ((size_t)b * NA + idx) * 7;
            float bx[7];
            decode_box(rg, an, bx);
            #pragma unroll
            for (int q = 0; q < 7; ++q) g_box[b][rank][q] = bx[q];
            g_score[b][rank] = 1.0f / (1.0f + expf(-unmapf(u)));
            float sx = fmaxf(bx[3], AUG);
            float sy = fmaxf(bx[4], AUG);
            float sz = fmaxf(bx[5], AUG);
            float lox = bx[0] - sx * 0.5f;
            g_geoA[b][rank] = make_float4(lox, bx[0] + sx * 0.5f,
                                          bx[1] - sy * 0.5f, bx[1] + sy * 0.5f);
            g_geoB[b][rank] = make_float4(bx[2], bx[2] + sz, sx * sy * sz,
                                          __int_as_float(rank));
            atomicAdd(&g_xcnt[b][xcell(lox)], 1u);
        }
    }

    __threadfence();
    __syncthreads();
    if (tid == 0) s_last = (atomicAdd(&g_done2[b], 1) == RCTA - 1) ? 1 : 0;
    __syncthreads();
    if (!s_last) return;

    // ---- cells tail with 1024 threads: prefix over 256 cells + 4-round scatter ----
    __shared__ int s_base[XBINS + 1];
    __shared__ unsigned s_val[XBINS];
    __shared__ unsigned s_cnt2[XBINS];
    if (tid < XBINS) {
        unsigned cnt = __ldcg(&g_xcnt[b][tid]);
        s_val[tid] = cnt;
        s_cnt2[tid] = 0u;
    }
    __syncthreads();
    if (tid < XBINS) {
        // single-warp-group Hillis-Steele on 256 entries (tid<256 threads)
        for (int d = 1; d < XBINS; d <<= 1) {
            unsigned v = (tid >= d) ? s_val[tid - d] : 0u;
            __syncthreads();
            s_val[tid] += v;
            __syncthreads();
        }
        unsigned cnt = __ldcg(&g_xcnt[b][tid]);
        s_base[tid] = (int)(s_val[tid] - cnt);
        if (tid == XBINS - 1) s_base[XBINS] = (int)s_val[XBINS - 1];
    } else {
        for (int d = 1; d < XBINS; d <<= 1) {
            __syncthreads();
            __syncthreads();
        }
    }
    __syncthreads();

    for (int r = tid; r < PRE; r += RTHR) {
        float4 a = __ldcg((const float4*)&g_geoA[b][r]);
        int cell = xcell(a.x);
        int pos = s_base[cell] + (int)atomicAdd(&s_cnt2[cell], 1u);
        g_sA[b][pos] = a;
        g_sB[b][pos] = __ldcg((const float4*)&g_geoB[b][r]);
    }
    __syncthreads();
    if (tid < XBINS) {
        g_xbase[b][tid] = s_base[tid];
        if (tid == XBINS - 1) g_xbase[b][XBINS] = s_base[XBINS];
    }
}

// ================= K4: sweep pairs (2 subwarps/slot), last CTA resolves + outputs =================
__global__ void __launch_bounds__(256) k_pairs_final(float* __restrict__ out) {
    __shared__ int s_last;
    const int tid = threadIdx.x;
    const int b = blockIdx.x / PB_CTA;
    const int cslice = blockIdx.x % PB_CTA;
    const int s = cslice * SLOTS_PER_CTA + (tid >> 6);   // spatial slot
    const int half = (tid >> 5) & 1;
    const int lane = tid & 31;

    {
        const float4 pA = g_sA[b][s];
        const float4 pB = g_sB[b][s];
        const int rp = __float_as_int(pB.w);
        const int end = g_xbase[b][xcell(pA.y) + 1];
        for (int q = s + 1 + half * 32 + lane; q < end; q += 64) {
            float4 qA = g_sA[b][q];
            float dxx = fminf(pA.y, qA.y) - fmaxf(pA.x, qA.x);
            if (dxx <= 0.f) continue;
            float dyy = fminf(pA.w, qA.w) - fmaxf(pA.z, qA.z);
            if (dyy <= 0.f) continue;
            float4 qB = g_sB[b][q];
            float dzz = fminf(pB.y, qB.y) - fmaxf(pB.x, qB.x);
            if (dzz <= 0.f) continue;
            float inter = dxx * dyy * dzz;
            float iou = inter / fmaxf(pB.z + qB.z - inter, 1e-8f);
            if (iou > NMS_TH) {
                int rq = __float_as_int(qB.w);
                int i = min(rp, rq), j = max(rp, rq);
                int p = atomicAdd(&g_pcnt[b], 1);
                if (p < PCAP) g_pairs[b][p] = ((unsigned)i << 16) | (unsigned)j;
            }
        }
    }

    // idle-time rezero of this batch's hist/bincnt/xcnt
    for (int i = cslice * 256 + tid; i < NBIN; i += PB_CTA * 256) {
        g_hist[b][i] = 0u;
        g_bincnt[b][i] = 0u;
    }
    if (cslice == 0 && tid < XBINS) g_xcnt[b][tid] = 0u;

    __threadfence();
    __syncthreads();
    if (tid == 0) s_last = (atomicAdd(&g_done3[b], 1) == PB_CTA - 1) ? 1 : 0;
    __syncthreads();
    if (!s_last) return;

    // ---- resolve + output (one CTA per batch) ----
    __shared__ unsigned pr[PCAP];
    __shared__ unsigned keepw[128];
    __shared__ int scan[126];
    __shared__ int order[POST];
    __shared__ int s_nk;

    int m = __ldcg(&g_pcnt[b]);
    if (m > PCAP) m = PCAP;
    int n2 = 32;
    while (n2 < m) n2 <<= 1;
    for (int i = tid; i < n2; i += 256)
        pr[i] = (i < m) ? __ldcg(&g_pairs[b][i]) : 0xFFFFFFFFu;
    __syncthreads();

    for (int k = 2; k <= n2; k <<= 1) {
        for (int jj = k >> 1; jj > 0; jj >>= 1) {
            for (int t = tid; t < n2; t += 256) {
                int ixj = t ^ jj;
                if (ixj > t) {
                    unsigned a = pr[t], c2 = pr[ixj];
                    bool up = ((t & k) == 0);
                    if (up ? (a > c2) : (a < c2)) { pr[t] = c2; pr[ixj] = a; }
                }
            }
            __syncthreads();
        }
    }

    for (int t = tid; t < 128; t += 256) keepw[t] = 0xFFFFFFFFu;
    __syncthreads();

    if (tid == 0) {
        for (int p = 0; p < m; ++p) {
            unsigned u = pr[p];
            int i = (int)(u >> 16);
            int j = (int)(u & 0xFFFFu);
            if ((keepw[i >> 5] >> (i & 31)) & 1u)
                keepw[j >> 5] &= ~(1u << (j & 31));
        }
        int run = 0;
        for (int w = 0; w < 125; ++w) {
            scan[w] = run;
            run += __popc(keepw[w]);
        }
        s_nk = run < POST ? run : POST;
        // counter resets for the next graph replay
        g_pcnt[b] = 0;
        g_done1[b] = 0;
        g_done2[b] = 0;
        g_done3[b] = 0;
    }
    __syncthreads();

    if (tid < 125) {
        unsigned w = keepw[tid];
        int base = scan[tid];
        while (w && base < POST) {
            int l = __ffs(w) - 1;
            w &= w - 1;
            order[base] = tid * 32 + l;
            ++base;
        }
    }
    __syncthreads();

    const int nk = s_nk;
    float* outb = out + (size_t)b * POST * 8;
    for (int r = tid; r < POST; r += 256) {
        float row[8];
        if (r < nk) {
            int rr = order[r];
            #pragma unroll
            for (int q = 0; q < 7; ++q) row[q] = g_box[b][rr][q];
            row[7] = g_score[b][rr];
        } else {
            #pragma unroll
            for (int q = 0; q < 8; ++q) row[q] = 0.f;
        }
        float4* o4 = (float4*)(outb + (size_t)r * 8);
        o4[0] = make_float4(row[0], row[1], row[2], row[3]);
        o4[1] = make_float4(row[4], row[5], row[6], row[7]);
    }
}

extern "C" void kernel_launch(void* const* d_in, const int* in_sizes, int n_in,
                              void* d_out, int out_size) {
    const float* obj = (const float*)d_in[0];
    const float* reg = (const float*)d_in[1];
    const float* anc = (const float*)d_in[2];
    float* out = (float*)d_out;

    k_hist<<<NB * HCTA, HTHR>>>(obj);
    k_scatter<<<NB * SCTA, STHR>>>(obj);
    k_rank<<<NB * RCTA, RTHR>>>(reg, anc);
    k_pairs_final<<<NB * PB_CTA, 256>>>(out);
}

// round 16
// speedup vs baseline: 1.4081x; 1.0165x over previous
#include <cuda_runtime.h>
#include <math.h>

#define NB 4
#define NA 262144
#define PRE 4000
#define POST 1000
#define NBIN 16384
#define BSHIFT 18
#define KCAP 8192
#define HCTA 64
#define HTHR 256
#define SCTA 128
#define STHR 256
#define RTHR 256
#define RCTA (KCAP / RTHR)   // 32
#define PCAP 4096
#define XBINS 256
#define XORG (-8.0f)
#define XSCL 4.0f
#define WPC 8                 // warps (slots) per pairs-CTA
#define PB_CTA (PRE / WPC)    // 500 pairs-CTAs per batch

static __device__ const float NMS_TH = 0.3f;
static __device__ const float AUG = 0.2f;

// ---- global scratch (zero-init; final tail re-zeroes everything dirtied) ----
__device__ unsigned g_hist[NB][NBIN];
__device__ unsigned g_bincnt[NB][NBIN];
__device__ int g_base[NB][NBIN];
__device__ unsigned g_selbin[NB];
__device__ int g_cc[NB];
__device__ int g_done1[NB];
__device__ int g_done2[NB];
__device__ int g_done3[NB];
__device__ unsigned long long g_keys2[NB][KCAP];
__device__ float4 g_geoA[NB][PRE];   // lox, hix, loy, hiy   (by rank)
__device__ float4 g_geoB[NB][PRE];   // loz, hiz, vol, rank  (by rank)
__device__ float4 g_sA[NB][PRE];     // spatially sorted copy
__device__ float4 g_sB[NB][PRE];
__device__ unsigned g_xcnt[NB][XBINS];
__device__ int g_xbase[NB][XBINS + 1];
__device__ float g_box[NB][PRE][7];
__device__ float g_score[NB][PRE];
__device__ unsigned g_pairs[NB][PCAP];
__device__ int g_pcnt[NB];

__device__ __forceinline__ unsigned mapf(float v) {
    unsigned u = __float_as_uint(v);
    return (u & 0x80000000u) ? ~u : (u | 0x80000000u);
}
__device__ __forceinline__ float unmapf(unsigned m) {
    return __uint_as_float((m & 0x80000000u) ? (m & 0x7FFFFFFFu) : ~m);
}
__device__ __forceinline__ int xcell(float v) {
    int c = (int)((v - XORG) * XSCL);
    return max(0, min(XBINS - 1, c));
}

// ================= K1: smem histogram + last-CTA suffix scan =================
__global__ void __launch_bounds__(HTHR) k_hist(const float* __restrict__ obj) {
    __shared__ unsigned sh[NBIN];
    __shared__ int s_last;
    const int b = blockIdx.x / HCTA;
    const int c = blockIdx.x % HCTA;
    const int tid = threadIdx.x;
    for (int i = tid; i < NBIN; i += HTHR) sh[i] = 0u;
    __syncthreads();
    const int CHUNK = NA / HCTA / 4;
    const float4* o4 = (const float4*)(obj + (size_t)b * NA) + (size_t)c * CHUNK;
    for (int i = tid; i < CHUNK; i += HTHR) {
        float4 v = o4[i];
        atomicAdd(&sh[mapf(v.x) >> BSHIFT], 1u);
        atomicAdd(&sh[mapf(v.y) >> BSHIFT], 1u);
        atomicAdd(&sh[mapf(v.z) >> BSHIFT], 1u);
        atomicAdd(&sh[mapf(v.w) >> BSHIFT], 1u);
    }
    __syncthreads();
    for (int i = tid; i < NBIN; i += HTHR) {
        unsigned cnt = sh[i];
        if (cnt) atomicAdd(&g_hist[b][i], cnt);
    }
    __threadfence();
    if (tid == 0) s_last = (atomicAdd(&g_done1[b], 1) == HCTA - 1) ? 1 : 0;
    __syncthreads();
    if (!s_last) return;

    __shared__ unsigned ssum[HTHR];
    const int CW = NBIN / HTHR;   // 64
    const int bi = tid * CW;
    unsigned loc[CW];
    unsigned csum = 0;
    #pragma unroll
    for (int k = 0; k < CW; ++k) {
        loc[k] = __ldcg(&g_hist[b][bi + k]);
        csum += loc[k];
    }
    unsigned orig = csum;
    ssum[tid] = csum;
    __syncthreads();
    for (int d = 1; d < HTHR; d <<= 1) {
        unsigned v = (tid + d < HTHR) ? ssum[tid + d] : 0u;
        __syncthreads();
        ssum[tid] += v;
        __syncthreads();
    }
    unsigned run = ssum[tid] - orig;
    for (int k = CW - 1; k >= 0; --k) {
        int bin = bi + k;
        g_base[b][bin] = (int)run;
        unsigned nb2 = run + loc[k];
        if (run < PRE && nb2 >= PRE) {
            g_selbin[b] = (unsigned)bin;
            g_cc[b] = (int)(nb2 < KCAP ? nb2 : KCAP);
        }
        run = nb2;
    }
}

// ================= K2: binned scatter of candidates =================
__global__ void __launch_bounds__(STHR) k_scatter(const float* __restrict__ obj) {
    const int b = blockIdx.x / SCTA;
    const int c = blockIdx.x % SCTA;
    const unsigned T = g_selbin[b] << BSHIFT;
    const int CHUNK = NA / SCTA / 4;
    const float4* o4 = (const float4*)(obj + (size_t)b * NA) + (size_t)c * CHUNK;
    for (int i = threadIdx.x; i < CHUNK; i += STHR) {
        float4 v = o4[i];
        unsigned uu[4] = {mapf(v.x), mapf(v.y), mapf(v.z), mapf(v.w)};
        int e0 = (c * CHUNK + i) * 4;
        #pragma unroll
        for (int q = 0; q < 4; ++q) {
            if (uu[q] >= T) {
                int bin = uu[q] >> BSHIFT;
                int slot = g_base[b][bin] + (int)atomicAdd(&g_bincnt[b][bin], 1u);
                if (slot < KCAP)
                    g_keys2[b][slot] =
                        ((unsigned long long)uu[q] << 32) | (unsigned)(~(e0 + q));
            }
        }
    }
}

// ================= K3: rank (prefetched decode) + last CTA cells tail =================
__global__ void __launch_bounds__(RTHR) k_rank(
    const float* __restrict__ reg, const float* __restrict__ anc)
{
    __shared__ int s_last;
    const int b = blockIdx.x / RCTA;
    const int c = blockIdx.x % RCTA;
    const int tid = threadIdx.x;
    const int cc = g_cc[b];
    const int s = c * RTHR + tid;

    if (s < cc) {
        const unsigned long long me = g_keys2[b][s];
        const unsigned u = (unsigned)(me >> 32);
        // ---- prefetch decode operands (overlaps with rank loop latency) ----
        const int idx = (int)(~(unsigned)(me & 0xFFFFFFFFull));
        const float* rg = reg + ((size_t)b * NA + idx) * 7;
        const float* an = anc + ((size_t)b * NA + idx) * 7;
        float d0 = rg[0], d1 = rg[1], d2 = rg[2], d3 = rg[3],
              d4 = rg[4], d5 = rg[5], d6 = rg[6];
        float a0 = an[0], a1 = an[1], a2 = an[2], a3 = an[3],
              a4 = an[4], a5 = an[5], a6 = an[6];

        const int bin = (int)(u >> BSHIFT);
        const int lo = g_base[b][bin];
        int hi = lo + (int)g_hist[b][bin];
        if (hi > cc) hi = cc;
        int rank = lo;
        const unsigned long long* kb = &g_keys2[b][0];
        int t = lo;
        for (; t + 4 <= hi; t += 4) {
            unsigned long long k0 = kb[t], k1 = kb[t + 1], k2 = kb[t + 2], k3 = kb[t + 3];
            rank += (k0 > me) + (k1 > me) + (k2 > me) + (k3 > me);
        }
        for (; t < hi; ++t) rank += (kb[t] > me);

        if (rank < PRE) {
            float diag = sqrtf(a3 * a3 + a4 * a4);
            float bx0 = d0 * diag + a0;
            float bx1 = d1 * diag + a1;
            float bx2 = d2 * a5 + a2;
            float bx3 = expf(d3) * a3;
            float bx4 = expf(d4) * a4;
            float bx5 = expf(d5) * a5;
            float bx6 = d6 + a6;
            float* bo = &g_box[b][rank][0];
            bo[0] = bx0; bo[1] = bx1; bo[2] = bx2; bo[3] = bx3;
            bo[4] = bx4; bo[5] = bx5; bo[6] = bx6;
            g_score[b][rank] = 1.0f / (1.0f + expf(-unmapf(u)));
            float sx = fmaxf(bx3, AUG);
            float sy = fmaxf(bx4, AUG);
            float sz = fmaxf(bx5, AUG);
            float lox = bx0 - sx * 0.5f;
            g_geoA[b][rank] = make_float4(lox, bx0 + sx * 0.5f,
                                          bx1 - sy * 0.5f, bx1 + sy * 0.5f);
            g_geoB[b][rank] = make_float4(bx2, bx2 + sz, sx * sy * sz,
                                          __int_as_float(rank));
            atomicAdd(&g_xcnt[b][xcell(lox)], 1u);
        }
    }

    __threadfence();
    __syncthreads();
    if (tid == 0) s_last = (atomicAdd(&g_done2[b], 1) == RCTA - 1) ? 1 : 0;
    __syncthreads();
    if (!s_last) return;

    // ---- x-cell prefix sum + spatial scatter (one CTA per batch) ----
    __shared__ int s_base[XBINS + 1];
    __shared__ unsigned s_val[XBINS];
    __shared__ unsigned s_cnt2[XBINS];
    unsigned cnt = __ldcg(&g_xcnt[b][tid]);
    s_val[tid] = cnt;
    s_cnt2[tid] = 0u;
    for (int d = 1; d < XBINS; d <<= 1) {
        __syncthreads();
        unsigned v = (tid >= d) ? s_val[tid - d] : 0u;
        __syncthreads();
        s_val[tid] += v;
    }
    __syncthreads();
    s_base[tid] = (int)(s_val[tid] - cnt);
    if (tid == XBINS - 1) s_base[XBINS] = (int)s_val[XBINS - 1];
    __syncthreads();

    for (int r = tid; r < PRE; r += RTHR) {
        float4 a = __ldcg((const float4*)&g_geoA[b][r]);
        int cell = xcell(a.x);
        int pos = s_base[cell] + (int)atomicAdd(&s_cnt2[cell], 1u);
        g_sA[b][pos] = a;
        g_sB[b][pos] = __ldcg((const float4*)&g_geoB[b][r]);
    }
    __syncthreads();
    g_xbase[b][tid] = s_base[tid];
    if (tid == XBINS - 1) g_xbase[b][XBINS] = s_base[XBINS];
}

// ================= K4: warp-per-slot sweep, last CTA resolves + outputs =================
__global__ void __launch_bounds__(256) k_pairs_final(float* __restrict__ out) {
    __shared__ int s_last;
    const int tid = threadIdx.x;
    const int b = blockIdx.x / PB_CTA;
    const int cslice = blockIdx.x % PB_CTA;
    const int s = cslice * WPC + (tid >> 5);   // spatial slot (warp-per-slot)
    const int lane = tid & 31;

    {
        const float4 pA = g_sA[b][s];
        const float4 pB = g_sB[b][s];
        const int rp = __float_as_int(pB.w);
        const int end = g_xbase[b][xcell(pA.y) + 1];
        for (int q = s + 1 + lane; q < end; q += 32) {
            float4 qA = g_sA[b][q];
            float dxx = fminf(pA.y, qA.y) - fmaxf(pA.x, qA.x);
            if (dxx <= 0.f) continue;
            float dyy = fminf(pA.w, qA.w) - fmaxf(pA.z, qA.z);
            if (dyy <= 0.f) continue;
            float4 qB = g_sB[b][q];
            float dzz = fminf(pB.y, qB.y) - fmaxf(pB.x, qB.x);
            if (dzz <= 0.f) continue;
            float inter = dxx * dyy * dzz;
            float iou = inter / fmaxf(pB.z + qB.z - inter, 1e-8f);
            if (iou > NMS_TH) {
                int rq = __float_as_int(qB.w);
                int i = min(rp, rq), j = max(rp, rq);
                int p = atomicAdd(&g_pcnt[b], 1);
                if (p < PCAP) g_pairs[b][p] = ((unsigned)i << 16) | (unsigned)j;
            }
        }
    }

    // idle-time rezero of this batch's hist/bincnt/xcnt
    for (int i = cslice * 256 + tid; i < NBIN; i += PB_CTA * 256) {
        g_hist[b][i] = 0u;
        g_bincnt[b][i] = 0u;
    }
    if (cslice == 0 && tid < XBINS) g_xcnt[b][tid] = 0u;

    __threadfence();
    __syncthreads();
    if (tid == 0) s_last = (atomicAdd(&g_done3[b], 1) == PB_CTA - 1) ? 1 : 0;
    __syncthreads();
    if (!s_last) return;

    // ---- resolve + output (one CTA per batch) ----
    __shared__ unsigned pr[PCAP];
    __shared__ unsigned keepw[128];
    __shared__ int scan[126];
    __shared__ int order[POST];
    __shared__ int s_nk;

    int m = __ldcg(&g_pcnt[b]);
    if (m > PCAP) m = PCAP;
    int n2 = 32;
    while (n2 < m) n2 <<= 1;
    for (int i = tid; i < n2; i += 256)
        pr[i] = (i < m) ? __ldcg(&g_pairs[b][i]) : 0xFFFFFFFFu;
    __syncthreads();

    for (int k = 2; k <= n2; k <<= 1) {
        for (int jj = k >> 1; jj > 0; jj >>= 1) {
            for (int t = tid; t < n2; t += 256) {
                int ixj = t ^ jj;
                if (ixj > t) {
                    unsigned a = pr[t], c2 = pr[ixj];
                    bool up = ((t & k) == 0);
                    if (up ? (a > c2) : (a < c2)) { pr[t] = c2; pr[ixj] = a; }
                }
            }
            __syncthreads();
        }
    }

    for (int t = tid; t < 128; t += 256) keepw[t] = 0xFFFFFFFFu;
    __syncthreads();

    if (tid == 0) {
        for (int p = 0; p < m; ++p) {
            unsigned u = pr[p];
            int i = (int)(u >> 16);
            int j = (int)(u & 0xFFFFu);
            if ((keepw[i >> 5] >> (i & 31)) & 1u)
                keepw[j >> 5] &= ~(1u << (j & 31));
        }
        int run = 0;
        for (int w = 0; w < 125; ++w) {
            scan[w] = run;
            run += __popc(keepw[w]);
        }
        s_nk = run < POST ? run : POST;
        // counter resets for the next graph replay
        g_pcnt[b] = 0;
        g_done1[b] = 0;
        g_done2[b] = 0;
        g_done3[b] = 0;
    }
    __syncthreads();

    if (tid < 125) {
        unsigned w = keepw[tid];
        int base = scan[tid];
        while (w && base < POST) {
            int l = __ffs(w) - 1;
            w &= w - 1;
            order[base] = tid * 32 + l;
            ++base;
        }
    }
    __syncthreads();

    const int nk = s_nk;
    float* outb = out + (size_t)b * POST * 8;
    for (int r = tid; r < POST; r += 256) {
        float row[8];
        if (r < nk) {
            int rr = order[r];
            #pragma unroll
            for (int q = 0; q < 7; ++q) row[q] = g_box[b][rr][q];
            row[7] = g_score[b][rr];
        } else {
            #pragma unroll
            for (int q = 0; q < 8; ++q) row[q] = 0.f;
        }
        float4* o4 = (float4*)(outb + (size_t)r * 8);
        o4[0] = make_float4(row[0], row[1], row[2], row[3]);
        o4[1] = make_float4(row[4], row[5], row[6], row[7]);
    }
}

extern "C" void kernel_launch(void* const* d_in, const int* in_sizes, int n_in,
                              void* d_out, int out_size) {
    const float* obj = (const float*)d_in[0];
    const float* reg = (const float*)d_in[1];
    const float* anc = (const float*)d_in[2];
    float* out = (float*)d_out;

    k_hist<<<NB * HCTA, HTHR>>>(obj);
    k_scatter<<<NB * SCTA, STHR>>>(obj);
    k_rank<<<NB * RCTA, RTHR>>>(reg, anc);
    k_pairs_final<<<NB * PB_CTA, 256>>>(out);
}

// round 17
// speedup vs baseline: 1.4469x; 1.0276x over previous
#include <cuda_runtime.h>
#include <math.h>

#define NB 4
#define NA 262144
#define PRE 4000
#define POST 1000
#define NBIN 16384
#define BSHIFT 18
#define KCAP 8192
#define HCTA 32
#define HTHR 256
#define SCTA 128
#define STHR 256
#define RTHR 256
#define RCTA (KCAP / RTHR)   // 32
#define PCAP 4096
#define XBINS 256
#define XORG (-8.0f)
#define XSCL 4.0f
#define WPC 8                 // warps (slots) per pairs-CTA
#define PB_CTA (PRE / WPC)    // 500 pairs-CTAs per batch

static __device__ const float NMS_TH = 0.3f;
static __device__ const float AUG = 0.2f;

#define GRIDDEP_WAIT() asm volatile("griddepcontrol.wait;" ::: "memory")

// ---- global scratch (zero-init; final tail re-zeroes everything dirtied) ----
__device__ unsigned g_hist[NB][NBIN];
__device__ unsigned g_bincnt[NB][NBIN];
__device__ int g_base[NB][NBIN];
__device__ unsigned g_selbin[NB];
__device__ int g_cc[NB];
__device__ int g_done1[NB];
__device__ int g_done2[NB];
__device__ int g_done3[NB];
__device__ unsigned long long g_keys2[NB][KCAP];
__device__ float4 g_geoA[NB][PRE];   // lox, hix, loy, hiy   (by rank)
__device__ float4 g_geoB[NB][PRE];   // loz, hiz, vol, rank  (by rank)
__device__ float4 g_sA[NB][PRE];     // spatially sorted copy
__device__ float4 g_sB[NB][PRE];
__device__ unsigned g_xcnt[NB][XBINS];
__device__ int g_xbase[NB][XBINS + 1];
__device__ float g_box[NB][PRE][7];
__device__ float g_score[NB][PRE];
__device__ unsigned g_pairs[NB][PCAP];
__device__ int g_pcnt[NB];

__device__ __forceinline__ unsigned mapf(float v) {
    unsigned u = __float_as_uint(v);
    return (u & 0x80000000u) ? ~u : (u | 0x80000000u);
}
__device__ __forceinline__ float unmapf(unsigned m) {
    return __uint_as_float((m & 0x80000000u) ? (m & 0x7FFFFFFFu) : ~m);
}
__device__ __forceinline__ int xcell(float v) {
    int c = (int)((v - XORG) * XSCL);
    return max(0, min(XBINS - 1, c));
}

// ================= K1: smem histogram + last-CTA suffix scan =================
__global__ void __launch_bounds__(HTHR) k_hist(const float* __restrict__ obj) {
    __shared__ unsigned sh[NBIN];
    __shared__ int s_last;
    const int b = blockIdx.x / HCTA;
    const int c = blockIdx.x % HCTA;
    const int tid = threadIdx.x;
    for (int i = tid; i < NBIN; i += HTHR) sh[i] = 0u;
    __syncthreads();
    const int CHUNK = NA / HCTA / 4;   // 2048 float4
    const float4* o4 = (const float4*)(obj + (size_t)b * NA) + (size_t)c * CHUNK;
    for (int i = tid; i < CHUNK; i += HTHR) {
        float4 v = o4[i];
        atomicAdd(&sh[mapf(v.x) >> BSHIFT], 1u);
        atomicAdd(&sh[mapf(v.y) >> BSHIFT], 1u);
        atomicAdd(&sh[mapf(v.z) >> BSHIFT], 1u);
        atomicAdd(&sh[mapf(v.w) >> BSHIFT], 1u);
    }
    __syncthreads();
    for (int i = tid; i < NBIN; i += HTHR) {
        unsigned cnt = sh[i];
        if (cnt) atomicAdd(&g_hist[b][i], cnt);
    }
    __threadfence();
    if (tid == 0) s_last = (atomicAdd(&g_done1[b], 1) == HCTA - 1) ? 1 : 0;
    __syncthreads();
    if (!s_last) return;

    __shared__ unsigned ssum[HTHR];
    const int CW = NBIN / HTHR;   // 64
    const int bi = tid * CW;
    unsigned loc[CW];
    unsigned csum = 0;
    #pragma unroll
    for (int k = 0; k < CW; ++k) {
        loc[k] = __ldcg(&g_hist[b][bi + k]);
        csum += loc[k];
    }
    unsigned orig = csum;
    ssum[tid] = csum;
    __syncthreads();
    for (int d = 1; d < HTHR; d <<= 1) {
        unsigned v = (tid + d < HTHR) ? ssum[tid + d] : 0u;
        __syncthreads();
        ssum[tid] += v;
        __syncthreads();
    }
    unsigned run = ssum[tid] - orig;
    for (int k = CW - 1; k >= 0; --k) {
        int bin = bi + k;
        g_base[b][bin] = (int)run;
        unsigned nb2 = run + loc[k];
        if (run < PRE && nb2 >= PRE) {
            g_selbin[b] = (unsigned)bin;
            g_cc[b] = (int)(nb2 < KCAP ? nb2 : KCAP);
        }
        run = nb2;
    }
}

// ================= K2: binned scatter of candidates (PDL) =================
__global__ void __launch_bounds__(STHR) k_scatter(const float* __restrict__ obj) {
    GRIDDEP_WAIT();
    const int b = blockIdx.x / SCTA;
    const int c = blockIdx.x % SCTA;
    const unsigned T = g_selbin[b] << BSHIFT;
    const int CHUNK = NA / SCTA / 4;
    const float4* o4 = (const float4*)(obj + (size_t)b * NA) + (size_t)c * CHUNK;
    for (int i = threadIdx.x; i < CHUNK; i += STHR) {
        float4 v = o4[i];
        unsigned uu[4] = {mapf(v.x), mapf(v.y), mapf(v.z), mapf(v.w)};
        int e0 = (c * CHUNK + i) * 4;
        #pragma unroll
        for (int q = 0; q < 4; ++q) {
            if (uu[q] >= T) {
                int bin = uu[q] >> BSHIFT;
                int slot = g_base[b][bin] + (int)atomicAdd(&g_bincnt[b][bin], 1u);
                if (slot < KCAP)
                    g_keys2[b][slot] =
                        ((unsigned long long)uu[q] << 32) | (unsigned)(~(e0 + q));
            }
        }
    }
}

// ================= K3: rank (prefetched decode) + last CTA cells tail (PDL) =================
__global__ void __launch_bounds__(RTHR) k_rank(
    const float* __restrict__ reg, const float* __restrict__ anc)
{
    __shared__ int s_last;
    const int b = blockIdx.x / RCTA;
    const int c = blockIdx.x % RCTA;
    const int tid = threadIdx.x;
    GRIDDEP_WAIT();
    const int cc = g_cc[b];
    const int s = c * RTHR + tid;

    if (s < cc) {
        const unsigned long long me = g_keys2[b][s];
        const unsigned u = (unsigned)(me >> 32);
        // prefetch decode operands (overlaps rank-loop latency)
        const int idx = (int)(~(unsigned)(me & 0xFFFFFFFFull));
        const float* rg = reg + ((size_t)b * NA + idx) * 7;
        const float* an = anc + ((size_t)b * NA + idx) * 7;
        float d0 = rg[0], d1 = rg[1], d2 = rg[2], d3 = rg[3],
              d4 = rg[4], d5 = rg[5], d6 = rg[6];
        float a0 = an[0], a1 = an[1], a2 = an[2], a3 = an[3],
              a4 = an[4], a5 = an[5], a6 = an[6];

        const int bin = (int)(u >> BSHIFT);
        const int lo = g_base[b][bin];
        int hi = lo + (int)g_hist[b][bin];
        if (hi > cc) hi = cc;
        int rank = lo;
        const unsigned long long* kb = &g_keys2[b][0];
        int t = lo;
        for (; t + 4 <= hi; t += 4) {
            unsigned long long k0 = kb[t], k1 = kb[t + 1], k2 = kb[t + 2], k3 = kb[t + 3];
            rank += (k0 > me) + (k1 > me) + (k2 > me) + (k3 > me);
        }
        for (; t < hi; ++t) rank += (kb[t] > me);

        if (rank < PRE) {
            float diag = sqrtf(a3 * a3 + a4 * a4);
            float bx0 = d0 * diag + a0;
            float bx1 = d1 * diag + a1;
            float bx2 = d2 * a5 + a2;
            float bx3 = expf(d3) * a3;
            float bx4 = expf(d4) * a4;
            float bx5 = expf(d5) * a5;
            float bx6 = d6 + a6;
            float* bo = &g_box[b][rank][0];
            bo[0] = bx0; bo[1] = bx1; bo[2] = bx2; bo[3] = bx3;
            bo[4] = bx4; bo[5] = bx5; bo[6] = bx6;
            g_score[b][rank] = 1.0f / (1.0f + expf(-unmapf(u)));
            float sx = fmaxf(bx3, AUG);
            float sy = fmaxf(bx4, AUG);
            float sz = fmaxf(bx5, AUG);
            float lox = bx0 - sx * 0.5f;
            g_geoA[b][rank] = make_float4(lox, bx0 + sx * 0.5f,
                                          bx1 - sy * 0.5f, bx1 + sy * 0.5f);
            g_geoB[b][rank] = make_float4(bx2, bx2 + sz, sx * sy * sz,
                                          __int_as_float(rank));
            atomicAdd(&g_xcnt[b][xcell(lox)], 1u);
        }
    }

    __threadfence();
    __syncthreads();
    if (tid == 0) s_last = (atomicAdd(&g_done2[b], 1) == RCTA - 1) ? 1 : 0;
    __syncthreads();
    if (!s_last) return;

    // ---- x-cell prefix sum + spatial scatter (one CTA per batch) ----
    __shared__ int s_base[XBINS + 1];
    __shared__ unsigned s_val[XBINS];
    __shared__ unsigned s_cnt2[XBINS];
    unsigned cnt = __ldcg(&g_xcnt[b][tid]);
    s_val[tid] = cnt;
    s_cnt2[tid] = 0u;
    for (int d = 1; d < XBINS; d <<= 1) {
        __syncthreads();
        unsigned v = (tid >= d) ? s_val[tid - d] : 0u;
        __syncthreads();
        s_val[tid] += v;
    }
    __syncthreads();
    s_base[tid] = (int)(s_val[tid] - cnt);
    if (tid == XBINS - 1) s_base[XBINS] = (int)s_val[XBINS - 1];
    __syncthreads();

    for (int r = tid; r < PRE; r += RTHR) {
        float4 a = __ldcg((const float4*)&g_geoA[b][r]);
        int cell = xcell(a.x);
        int pos = s_base[cell] + (int)atomicAdd(&s_cnt2[cell], 1u);
        g_sA[b][pos] = a;
        g_sB[b][pos] = __ldcg((const float4*)&g_geoB[b][r]);
    }
    __syncthreads();
    g_xbase[b][tid] = s_base[tid];
    if (tid == XBINS - 1) g_xbase[b][XBINS] = s_base[XBINS];
}

// ================= K4: warp-per-slot sweep, last CTA resolves + outputs (PDL) =================
__global__ void __launch_bounds__(256) k_pairs_final(float* __restrict__ out) {
    __shared__ int s_last;
    const int tid = threadIdx.x;
    const int b = blockIdx.x / PB_CTA;
    const int cslice = blockIdx.x % PB_CTA;
    const int s = cslice * WPC + (tid >> 5);   // spatial slot (warp-per-slot)
    const int lane = tid & 31;
    GRIDDEP_WAIT();

    {
        const float4 pA = g_sA[b][s];
        const float4 pB = g_sB[b][s];
        const int rp = __float_as_int(pB.w);
        const int end = g_xbase[b][xcell(pA.y) + 1];
        for (int q = s + 1 + lane; q < end; q += 32) {
            float4 qA = g_sA[b][q];
            float dxx = fminf(pA.y, qA.y) - fmaxf(pA.x, qA.x);
            if (dxx <= 0.f) continue;
            float dyy = fminf(pA.w, qA.w) - fmaxf(pA.z, qA.z);
            if (dyy <= 0.f) continue;
            float4 qB = g_sB[b][q];
            float dzz = fminf(pB.y, qB.y) - fmaxf(pB.x, qB.x);
            if (dzz <= 0.f) continue;
            float inter = dxx * dyy * dzz;
            float iou = inter / fmaxf(pB.z + qB.z - inter, 1e-8f);
            if (iou > NMS_TH) {
                int rq = __float_as_int(qB.w);
                int i = min(rp, rq), j = max(rp, rq);
                int p = atomicAdd(&g_pcnt[b], 1);
                if (p < PCAP) g_pairs[b][p] = ((unsigned)i << 16) | (unsigned)j;
            }
        }
    }

    // idle-time rezero of this batch's hist/bincnt/xcnt
    for (int i = cslice * 256 + tid; i < NBIN; i += PB_CTA * 256) {
        g_hist[b][i] = 0u;
        g_bincnt[b][i] = 0u;
    }
    if (cslice == 0 && tid < XBINS) g_xcnt[b][tid] = 0u;

    __threadfence();
    __syncthreads();
    if (tid == 0) s_last = (atomicAdd(&g_done3[b], 1) == PB_CTA - 1) ? 1 : 0;
    __syncthreads();
    if (!s_last) return;

    // ---- resolve + output (one CTA per batch) ----
    __shared__ unsigned pr[PCAP];
    __shared__ unsigned keepw[128];
    __shared__ int scan[126];
    __shared__ int order[POST];
    __shared__ int s_nk;

    int m = __ldcg(&g_pcnt[b]);
    if (m > PCAP) m = PCAP;
    int n2 = 32;
    while (n2 < m) n2 <<= 1;
    for (int i = tid; i < n2; i += 256)
        pr[i] = (i < m) ? __ldcg(&g_pairs[b][i]) : 0xFFFFFFFFu;
    __syncthreads();

    for (int k = 2; k <= n2; k <<= 1) {
        for (int jj = k >> 1; jj > 0; jj >>= 1) {
            for (int t = tid; t < n2; t += 256) {
                int ixj = t ^ jj;
                if (ixj > t) {
                    unsigned a = pr[t], c2 = pr[ixj];
                    bool up = ((t & k) == 0);
                    if (up ? (a > c2) : (a < c2)) { pr[t] = c2; pr[ixj] = a; }
                }
            }
            __syncthreads();
        }
    }

    for (int t = tid; t < 128; t += 256) keepw[t] = 0xFFFFFFFFu;
    __syncthreads();

    if (tid == 0) {
        for (int p = 0; p < m; ++p) {
            unsigned u = pr[p];
            int i = (int)(u >> 16);
            int j = (int)(u & 0xFFFFu);
            if ((keepw[i >> 5] >> (i & 31)) & 1u)
                keepw[j >> 5] &= ~(1u << (j & 31));
        }
        int run = 0;
        for (int w = 0; w < 125; ++w) {
            scan[w] = run;
            run += __popc(keepw[w]);
        }
        s_nk = run < POST ? run : POST;
        g_pcnt[b] = 0;
        g_done1[b] = 0;
        g_done2[b] = 0;
        g_done3[b] = 0;
    }
    __syncthreads();

    if (tid < 125) {
        unsigned w = keepw[tid];
        int base = scan[tid];
        while (w && base < POST) {
            int l = __ffs(w) - 1;
            w &= w - 1;
            order[base] = tid * 32 + l;
            ++base;
        }
    }
    __syncthreads();

    const int nk = s_nk;
    float* outb = out + (size_t)b * POST * 8;
    for (int r = tid; r < POST; r += 256) {
        float row[8];
        if (r < nk) {
            int rr = order[r];
            #pragma unroll
            for (int q = 0; q < 7; ++q) row[q] = g_box[b][rr][q];
            row[7] = g_score[b][rr];
        } else {
            #pragma unroll
            for (int q = 0; q < 8; ++q) row[q] = 0.f;
        }
        float4* o4 = (float4*)(outb + (size_t)r * 8);
        o4[0] = make_float4(row[0], row[1], row[2], row[3]);
        o4[1] = make_float4(row[4], row[5], row[6], row[7]);
    }
}

extern "C" void kernel_launch(void* const* d_in, const int* in_sizes, int n_in,
                              void* d_out, int out_size) {
    const float* obj = (const float*)d_in[0];
    const float* reg = (const float*)d_in[1];
    const float* anc = (const float*)d_in[2];
    float* out = (float*)d_out;

    k_hist<<<NB * HCTA, HTHR>>>(obj);

    cudaLaunchAttribute at[1];
    at[0].id = cudaLaunchAttributeProgrammaticStreamSerialization;
    at[0].val.programmaticStreamSerializationAllowed = 1;

    cudaLaunchConfig_t cfg = {};
    cfg.attrs = at;
    cfg.numAttrs = 1;

    cfg.gridDim = dim3(NB * SCTA);
    cfg.blockDim = dim3(STHR);
    cudaLaunchKernelEx(&cfg, k_scatter, obj);

    cfg.gridDim = dim3(NB * RCTA);
    cfg.blockDim = dim3(RTHR);
    cudaLaunchKernelEx(&cfg, k_rank, reg, anc);

    cfg.gridDim = dim3(NB * PB_CTA);
    cfg.blockDim = dim3(256);
    cudaLaunchKernelEx(&cfg, k_pairs_final, out);
}